// round 5
// baseline (speedup 1.0000x reference)
#include <cuda_runtime.h>
#include <cuda_fp16.h>
#include <cuda_bf16.h>

#define BB 4
#define CC 64
#define LL 4096
#define CQ 16
#define NH 4
#define NB 32
#define TJ 128
#define EPSV 1e-5f
#define SHIFT 20.0f
#define PTOK 32                 // k_proj tokens per block
#define NPB (BB*(LL/PTOK))      // 512 proj blocks -> stat partials

// ---------------- scratch (device globals; no allocation at runtime) ----------------
__device__ float g_q[BB*LL*CQ];
__device__ float g_k[BB*LL*CQ];
__device__ float g_v[BB*LL*CC];
__device__ int   g_sorted[BB*NH*LL];
__device__ int   g_bstart[BB*NH*(NB+1)];
__device__ __align__(16) __half g_acch[NH*BB*LL*CC];
__device__ float g_pre[BB*CC*LL];
__device__ float g_psum[CC*NPB];
__device__ float g_psq[CC*NPB];
__device__ float g_ss[2*CC];

// ---------------- packed f32x2 helpers ----------------
__device__ __forceinline__ unsigned long long ffma2(unsigned long long a,
                                                    unsigned long long b,
                                                    unsigned long long c) {
    unsigned long long d;
    asm("fma.rn.f32x2 %0, %1, %2, %3;" : "=l"(d) : "l"(a), "l"(b), "l"(c));
    return d;
}
__device__ __forceinline__ unsigned long long addf2(unsigned long long a,
                                                    unsigned long long b) {
    unsigned long long d;
    asm("add.rn.f32x2 %0, %1, %2;" : "=l"(d) : "l"(a), "l"(b));
    return d;
}
__device__ __forceinline__ unsigned long long pack2(float lo, float hi) {
    unsigned long long r;
    asm("mov.b64 %0, {%1, %2};" : "=l"(r)
        : "r"(__float_as_uint(lo)), "r"(__float_as_uint(hi)));
    return r;
}
__device__ __forceinline__ void unpack2(unsigned long long v, float& lo, float& hi) {
    unsigned int a, b;
    asm("mov.b64 {%0, %1}, %2;" : "=r"(a), "=r"(b) : "l"(v));
    lo = __uint_as_float(a); hi = __uint_as_float(b);
}

// ---------------- K1: fused qkv convs (z<6) + bucket sort (z==6) ----------------
__global__ void __launch_bounds__(256) k_pre(const float* __restrict__ x,
    const int* __restrict__ hash,
    const float* __restrict__ Wq, const float* __restrict__ bq,
    const float* __restrict__ Wk, const float* __restrict__ bk,
    const float* __restrict__ Wv, const float* __restrict__ bv)
{
    const int t = threadIdx.x;
    const int z = blockIdx.z;

    if (z == 6) {
        // -------- bucket counting sort for (h, b) --------
        if (blockIdx.x >= NH) return;
        const int h = blockIdx.x, b = blockIdx.y;
        const int* hb = hash + ((size_t)b*NH + h)*LL;

        __shared__ unsigned short cnt[256][NB];
        __shared__ int tot[NB];
        __shared__ int bstart[NB+1];

        for (int k = 0; k < NB; k++) cnt[t][k] = 0;
        __syncthreads();

        const int base = t * 16;
#pragma unroll
        for (int e = 0; e < 16; e++) cnt[t][hb[base + e]]++;
        __syncthreads();

        if (t < NB) {
            int s = 0;
            for (int r = 0; r < 256; r++) {
                unsigned short v = cnt[r][t];
                cnt[r][t] = (unsigned short)s;
                s += v;
            }
            tot[t] = s;
        }
        __syncthreads();
        if (t == 0) {
            int s = 0;
            for (int k = 0; k < NB; k++) { bstart[k] = s; s += tot[k]; }
            bstart[NB] = s;
        }
        __syncthreads();
        if (t < NB + 1) g_bstart[((size_t)b*NH + h)*(NB+1) + t] = bstart[t];

        int* out = g_sorted + ((size_t)b*NH + h)*LL;
#pragma unroll
        for (int e = 0; e < 16; e++) {
            int l = base + e;
            int bk = hb[l];
            out[bstart[bk] + cnt[t][bk]] = l;
            cnt[t][bk]++;
        }
        return;
    }

    // -------- qkv 1x1 conv slice (16 output channels) --------
    __shared__ __align__(16) float sW[16*CC];
    __shared__ float sb[16];
    const int b = blockIdx.y;
    const int l = blockIdx.x * 256 + t;

    const float* W; const float* bias;
    if (z == 0)      { W = Wq; bias = bq; }
    else if (z == 1) { W = Wk; bias = bk; }
    else             { W = Wv + (z-2)*16*CC; bias = bv + (z-2)*16; }
    for (int i = t; i < 16*CC; i += 256) sW[i] = W[i];
    if (t < 16) sb[t] = bias[t];
    __syncthreads();

    const float* xb = x + (size_t)b*CC*LL + l;
    float xr[CC];
#pragma unroll
    for (int c = 0; c < CC; c++) xr[c] = xb[(size_t)c*LL];

    float out[16];
#pragma unroll 4
    for (int o = 0; o < 16; o++) {
        float a = sb[o];
        const float4* w = (const float4*)&sW[o*CC];
#pragma unroll
        for (int c4 = 0; c4 < CC/4; c4++) {
            float4 w4 = w[c4];
            a += w4.x*xr[4*c4] + w4.y*xr[4*c4+1] + w4.z*xr[4*c4+2] + w4.w*xr[4*c4+3];
        }
        out[o] = a;
    }

    float4* dst;
    if (z == 0)      dst = (float4*)(g_q + ((size_t)b*LL + l)*CQ);
    else if (z == 1) dst = (float4*)(g_k + ((size_t)b*LL + l)*CQ);
    else             dst = (float4*)(g_v + ((size_t)b*LL + l)*CC + (z-2)*16);
#pragma unroll
    for (int i = 0; i < 4; i++)
        dst[i] = make_float4(out[4*i], out[4*i+1], out[4*i+2], out[4*i+3]);
}

// ---------------- K2: bucket softmax attention, key-split x2 ----------------
__global__ void __launch_bounds__(256) k_attn()
{
    const int bucket = blockIdx.x, h = blockIdx.y, b = blockIdx.z;
    const int bh = b*NH + h;
    const int start = g_bstart[bh*(NB+1) + bucket];
    const int end   = g_bstart[bh*(NB+1) + bucket + 1];
    const int n = end - start;
    if (n <= 0) return;

    const int* __restrict__ sorted = g_sorted + (size_t)bh*LL + start;
    const float* __restrict__ kb = g_k + (size_t)b*LL*CQ;
    const float* __restrict__ vb = g_v + (size_t)b*LL*CC;
    const float* __restrict__ qb = g_q + (size_t)b*LL*CQ;
    __half* __restrict__ ab = g_acch + (((size_t)h*BB + b)*LL)*CC;

    __shared__ __align__(16) float s_k[TJ*CQ];     // 8KB  (also Z exchange)
    __shared__ __align__(16) float s_v[TJ*CC];     // 32KB (also acc exchange)

    const int tid  = threadIdx.x;
    const int grp  = tid >> 7;       // 0 or 1: key-half
    const int gtid = tid & 127;      // query slot within tile

    const int half = (n + 1) >> 1;
    const int klo  = grp ? half : 0;
    const int khi  = grp ? n    : half;

    for (int q0 = 0; q0 < n; q0 += 128) {
        const int qi = q0 + gtid;
        const bool act = qi < n;
        int gi = 0;
        unsigned long long q2[CQ/2];
        if (act) {
            gi = sorted[qi];
            const float4* qs = (const float4*)(qb + (size_t)gi*CQ);
#pragma unroll
            for (int c4 = 0; c4 < CQ/4; c4++) {
                float4 v4 = qs[c4];
                q2[2*c4]   = pack2(v4.x, v4.y);
                q2[2*c4+1] = pack2(v4.z, v4.w);
            }
        }

        unsigned long long acc2[CC/2];
#pragma unroll
        for (int c = 0; c < CC/2; c++) acc2[c] = 0ull;
        float Z = 0.f;

        for (int j0 = 0; j0 < n; j0 += TJ) {
            const int tj = min(TJ, n - j0);
            __syncthreads();
            for (int t = tid; t < tj*(CQ/4); t += 256) {
                int r = t >> 2, c4 = t & 3;
                ((float4*)s_k)[t] = ((const float4*)(kb + (size_t)sorted[j0 + r]*CQ))[c4];
            }
            for (int t = tid; t < tj*(CC/4); t += 256) {
                int r = t >> 4, c4 = t & 15;
                ((float4*)s_v)[(r*(CC/4)) + c4] = ((const float4*)(vb + (size_t)sorted[j0 + r]*CC))[c4];
            }
            __syncthreads();
            const int jlo = max(0, klo - j0);
            const int jhi = min(tj, khi - j0);
            if (act) {
                for (int j = jlo; j < jhi; j++) {
                    const ulonglong2* kk = (const ulonglong2*)(s_k + j*CQ);
                    unsigned long long s2 = 0ull;
#pragma unroll
                    for (int c = 0; c < CQ/4; c++) {
                        ulonglong2 kp = kk[c];
                        s2 = ffma2(q2[2*c],   kp.x, s2);
                        s2 = ffma2(q2[2*c+1], kp.y, s2);
                    }
                    float slo, shi; unpack2(s2, slo, shi);
                    float w = __expf(slo + shi - SHIFT);
                    Z += w;
                    unsigned long long w2 = pack2(w, w);
                    const ulonglong2* vv = (const ulonglong2*)(s_v + j*CC);
#pragma unroll
                    for (int c = 0; c < CC/4; c++) {
                        ulonglong2 vp = vv[c];
                        acc2[2*c]   = ffma2(w2, vp.x, acc2[2*c]);
                        acc2[2*c+1] = ffma2(w2, vp.y, acc2[2*c+1]);
                    }
                }
            }
        }

        // combine group1 partials into group0 (deterministic order)
        __syncthreads();
        if (grp == 1) {
            s_k[gtid] = Z;
            unsigned long long* ex = (unsigned long long*)s_v;
#pragma unroll
            for (int c = 0; c < CC/2; c++) ex[c*128 + gtid] = acc2[c];
        }
        __syncthreads();
        if (grp == 0 && act) {
            Z += s_k[gtid];
            const unsigned long long* ex = (const unsigned long long*)s_v;
#pragma unroll
            for (int c = 0; c < CC/2; c++) acc2[c] = addf2(acc2[c], ex[c*128 + gtid]);

            float inv = 1.0f / Z;
            unsigned int hw[CC/2];
#pragma unroll
            for (int c = 0; c < CC/2; c++) {
                float a0, a1; unpack2(acc2[c], a0, a1);
                __half2 h2 = __floats2half2_rn(a0*inv, a1*inv);
                hw[c] = *(unsigned int*)&h2;
            }
            uint4* ap = (uint4*)(ab + (size_t)gi*CC);
#pragma unroll
            for (int g = 0; g < CC/8; g++)
                ap[g] = make_uint4(hw[4*g], hw[4*g+1], hw[4*g+2], hw[4*g+3]);
        }
    }
}

// ---------------- K3: projection + residual + fused stats (32-token tiles) ----------------
__global__ void __launch_bounds__(256) k_proj(const float* __restrict__ x,
    const float* __restrict__ Wo, const float* __restrict__ bo,
    const float* __restrict__ gamma)
{
    __shared__ __align__(16) float sA[PTOK*65];
    __shared__ __align__(16) float sW[CC*CC];
    const int t = threadIdx.x;
    const int b = blockIdx.y;
    const int l0 = blockIdx.x * PTOK;

    for (int i = t; i < CC*CC; i += 256) sW[i] = Wo[i];
    {
        const size_t base2 = (((size_t)b*LL + l0)*CC) >> 1;
        const size_t plane = ((size_t)BB*LL*CC) >> 1;
        const __half2* A = (const __half2*)g_acch;
        for (int i = t; i < PTOK*(CC/2); i += 256) {
            float2 f0 = __half22float2(A[0*plane + base2 + i]);
            float2 f1 = __half22float2(A[1*plane + base2 + i]);
            float2 f2 = __half22float2(A[2*plane + base2 + i]);
            float2 f3 = __half22float2(A[3*plane + base2 + i]);
            int tok = i >> 5, c2 = i & 31;
            sA[tok*65 + 2*c2]     = (f0.x + f1.x + f2.x + f3.x) * 0.25f;
            sA[tok*65 + 2*c2 + 1] = (f0.y + f1.y + f2.y + f3.y) * 0.25f;
        }
    }
    __syncthreads();

    const int w  = t >> 5;   // warp -> channels w*8..w*8+7
    const int ln = t & 31;   // token lane
    const float g = gamma[0];

    float acc[8];
#pragma unroll
    for (int k = 0; k < 8; k++) acc[k] = bo[w*8 + k];

#pragma unroll 4
    for (int cin = 0; cin < CC; cin++) {
        float a = sA[ln*65 + cin];
#pragma unroll
        for (int k = 0; k < 8; k++) acc[k] += sW[(w*8 + k)*CC + cin] * a;
    }

    const int blk = b*(LL/PTOK) + blockIdx.x;
#pragma unroll
    for (int k = 0; k < 8; k++) {
        int c = w*8 + k;
        size_t i1 = ((size_t)b*CC + c)*LL + l0 + ln;
        float o1 = g*acc[k] + x[i1];
        g_pre[i1] = o1;
        float s = o1, sq = o1*o1;
#pragma unroll
        for (int off = 16; off > 0; off >>= 1) {
            s  += __shfl_down_sync(0xffffffffu, s,  off);
            sq += __shfl_down_sync(0xffffffffu, sq, off);
        }
        if (ln == 0) {
            g_psum[c*NPB + blk] = s;
            g_psq [c*NPB + blk] = sq;
        }
    }
}

// ---------------- K4: finalize per-channel scale/shift ----------------
__global__ void __launch_bounds__(256) k_finstat(const float* __restrict__ bn_w,
                                                 const float* __restrict__ bn_b)
{
    const int c = blockIdx.x, t = threadIdx.x;
    __shared__ double rs[256], rs2[256];
    rs[t]  = (double)g_psum[c*NPB + t] + (double)g_psum[c*NPB + 256 + t];
    rs2[t] = (double)g_psq [c*NPB + t] + (double)g_psq [c*NPB + 256 + t];
    __syncthreads();
    for (int o = 128; o > 0; o >>= 1) {
        if (t < o) { rs[t] += rs[t+o]; rs2[t] += rs2[t+o]; }
        __syncthreads();
    }
    if (t == 0) {
        double mean = rs[0] * (1.0/(BB*LL));
        double var  = rs2[0] * (1.0/(BB*LL)) - mean*mean;
        float rstd = rsqrtf((float)var + EPSV);
        float sc = rstd * bn_w[c];
        g_ss[2*c]   = sc;
        g_ss[2*c+1] = bn_b[c] - (float)mean * sc;
    }
}

// ---------------- K5: batchnorm apply ----------------
__global__ void __launch_bounds__(256) k_norm(float* __restrict__ out)
{
    const int i4 = blockIdx.x * 256 + threadIdx.x;
    const int c = (i4 >> 10) & (CC - 1);
    const float sc = g_ss[2*c], sh = g_ss[2*c+1];
    float4 p = ((const float4*)g_pre)[i4];
    ((float4*)out)[i4] = make_float4(p.x*sc + sh, p.y*sc + sh, p.z*sc + sh, p.w*sc + sh);
}

// ---------------- launch ----------------
extern "C" void kernel_launch(void* const* d_in, const int* in_sizes, int n_in,
                              void* d_out, int out_size)
{
    const float* x     = (const float*)d_in[0];
    const int*   hash  = (const int*)  d_in[1];
    const float* Wq    = (const float*)d_in[2];
    const float* bq    = (const float*)d_in[3];
    const float* Wk    = (const float*)d_in[4];
    const float* bk    = (const float*)d_in[5];
    const float* Wv    = (const float*)d_in[6];
    const float* bv    = (const float*)d_in[7];
    const float* Wo    = (const float*)d_in[8];
    const float* bo    = (const float*)d_in[9];
    const float* gamma = (const float*)d_in[10];
    const float* bnw   = (const float*)d_in[11];
    const float* bnb   = (const float*)d_in[12];
    float* out = (float*)d_out;

    k_pre   <<<dim3(LL/256, BB, 7), 256>>>(x, hash, Wq, bq, Wk, bk, Wv, bv);
    k_attn  <<<dim3(NB, NH, BB), 256>>>();
    k_proj  <<<dim3(LL/PTOK, BB), 256>>>(x, Wo, bo, gamma);
    k_finstat<<<CC, 256>>>(bnw, bnb);
    k_norm  <<<(BB*CC*LL)/(4*256), 256>>>(out);
}

// round 6
// speedup vs baseline: 1.0814x; 1.0814x over previous
#include <cuda_runtime.h>
#include <cuda_fp16.h>
#include <cuda_bf16.h>

#define BB 4
#define CC 64
#define LL 4096
#define CQ 16
#define NH 4
#define NB 32
#define TJ 128
#define EPSV 1e-5f
#define SHIFT 20.0f
#define PTOK 64                 // k_proj tokens per block
#define NPB (BB*(LL/PTOK))      // 256 proj blocks -> stat partials

// ---------------- scratch (device globals; no allocation at runtime) ----------------
__device__ float g_q[BB*LL*CQ];
__device__ float g_k[BB*LL*CQ];
__device__ float g_v[BB*LL*CC];
__device__ int   g_sorted[BB*NH*LL];
__device__ int   g_bstart[BB*NH*(NB+1)];
__device__ __align__(16) __half g_acch[NH*BB*LL*CC];
__device__ float g_pre[BB*CC*LL];
__device__ float g_psum[CC*NPB];
__device__ float g_psq[CC*NPB];

// ---------------- packed f32x2 helpers ----------------
__device__ __forceinline__ unsigned long long ffma2(unsigned long long a,
                                                    unsigned long long b,
                                                    unsigned long long c) {
    unsigned long long d;
    asm("fma.rn.f32x2 %0, %1, %2, %3;" : "=l"(d) : "l"(a), "l"(b), "l"(c));
    return d;
}
__device__ __forceinline__ unsigned long long pack2(float lo, float hi) {
    unsigned long long r;
    asm("mov.b64 %0, {%1, %2};" : "=l"(r)
        : "r"(__float_as_uint(lo)), "r"(__float_as_uint(hi)));
    return r;
}
__device__ __forceinline__ void unpack2(unsigned long long v, float& lo, float& hi) {
    unsigned int a, b;
    asm("mov.b64 {%0, %1}, %2;" : "=r"(a), "=r"(b) : "l"(v));
    lo = __uint_as_float(a); hi = __uint_as_float(b);
}

// ---------------- K1: fused qkv convs (z<6) + bucket sort (z==6) ----------------
__global__ void __launch_bounds__(256) k_pre(const float* __restrict__ x,
    const int* __restrict__ hash,
    const float* __restrict__ Wq, const float* __restrict__ bq,
    const float* __restrict__ Wk, const float* __restrict__ bk,
    const float* __restrict__ Wv, const float* __restrict__ bv)
{
    const int t = threadIdx.x;
    const int z = blockIdx.z;

    if (z == 6) {
        if (blockIdx.x >= NH) return;
        const int h = blockIdx.x, b = blockIdx.y;
        const int* hb = hash + ((size_t)b*NH + h)*LL;

        __shared__ unsigned short cnt[256][NB];
        __shared__ int tot[NB];
        __shared__ int bstart[NB+1];

        for (int k = 0; k < NB; k++) cnt[t][k] = 0;
        __syncthreads();

        const int base = t * 16;
#pragma unroll
        for (int e = 0; e < 16; e++) cnt[t][hb[base + e]]++;
        __syncthreads();

        if (t < NB) {
            int s = 0;
            for (int r = 0; r < 256; r++) {
                unsigned short v = cnt[r][t];
                cnt[r][t] = (unsigned short)s;
                s += v;
            }
            tot[t] = s;
        }
        __syncthreads();
        if (t == 0) {
            int s = 0;
            for (int k = 0; k < NB; k++) { bstart[k] = s; s += tot[k]; }
            bstart[NB] = s;
        }
        __syncthreads();
        if (t < NB + 1) g_bstart[((size_t)b*NH + h)*(NB+1) + t] = bstart[t];

        int* out = g_sorted + ((size_t)b*NH + h)*LL;
#pragma unroll
        for (int e = 0; e < 16; e++) {
            int l = base + e;
            int bk = hb[l];
            out[bstart[bk] + cnt[t][bk]] = l;
            cnt[t][bk]++;
        }
        return;
    }

    __shared__ __align__(16) float sW[16*CC];
    __shared__ float sb[16];
    const int b = blockIdx.y;
    const int l = blockIdx.x * 256 + t;

    const float* W; const float* bias;
    if (z == 0)      { W = Wq; bias = bq; }
    else if (z == 1) { W = Wk; bias = bk; }
    else             { W = Wv + (z-2)*16*CC; bias = bv + (z-2)*16; }
    for (int i = t; i < 16*CC; i += 256) sW[i] = W[i];
    if (t < 16) sb[t] = bias[t];
    __syncthreads();

    const float* xb = x + (size_t)b*CC*LL + l;
    float xr[CC];
#pragma unroll
    for (int c = 0; c < CC; c++) xr[c] = xb[(size_t)c*LL];

    float out[16];
#pragma unroll 4
    for (int o = 0; o < 16; o++) {
        float a = sb[o];
        const float4* w = (const float4*)&sW[o*CC];
#pragma unroll
        for (int c4 = 0; c4 < CC/4; c4++) {
            float4 w4 = w[c4];
            a += w4.x*xr[4*c4] + w4.y*xr[4*c4+1] + w4.z*xr[4*c4+2] + w4.w*xr[4*c4+3];
        }
        out[o] = a;
    }

    float4* dst;
    if (z == 0)      dst = (float4*)(g_q + ((size_t)b*LL + l)*CQ);
    else if (z == 1) dst = (float4*)(g_k + ((size_t)b*LL + l)*CQ);
    else             dst = (float4*)(g_v + ((size_t)b*LL + l)*CC + (z-2)*16);
#pragma unroll
    for (int i = 0; i < 4; i++)
        dst[i] = make_float4(out[4*i], out[4*i+1], out[4*i+2], out[4*i+3]);
}

// ---------------- K2: single-pass bucket softmax attention (128 thr) ----------------
__global__ void __launch_bounds__(128) k_attn()
{
    const int bucket = blockIdx.x, h = blockIdx.y, b = blockIdx.z;
    const int bh = b*NH + h;
    const int start = g_bstart[bh*(NB+1) + bucket];
    const int end   = g_bstart[bh*(NB+1) + bucket + 1];
    const int n = end - start;
    if (n <= 0) return;

    const int* __restrict__ sorted = g_sorted + (size_t)bh*LL + start;
    const float* __restrict__ kb = g_k + (size_t)b*LL*CQ;
    const float* __restrict__ vb = g_v + (size_t)b*LL*CC;
    const float* __restrict__ qb = g_q + (size_t)b*LL*CQ;
    __half* __restrict__ ab = g_acch + (((size_t)h*BB + b)*LL)*CC;

    __shared__ __align__(16) float s_k[TJ*CQ];
    __shared__ __align__(16) float s_v[TJ*CC];

    const int tid = threadIdx.x;

    for (int q0 = 0; q0 < n; q0 += 128) {
        const int qi = q0 + tid;
        const bool act = qi < n;
        int gi = 0;
        unsigned long long q2[CQ/2];
        if (act) {
            gi = sorted[qi];
            const float4* qs = (const float4*)(qb + (size_t)gi*CQ);
#pragma unroll
            for (int c4 = 0; c4 < CQ/4; c4++) {
                float4 v4 = qs[c4];
                q2[2*c4]   = pack2(v4.x, v4.y);
                q2[2*c4+1] = pack2(v4.z, v4.w);
            }
        }

        unsigned long long acc2[CC/2];
#pragma unroll
        for (int c = 0; c < CC/2; c++) acc2[c] = 0ull;
        float Z = 0.f;

        for (int j0 = 0; j0 < n; j0 += TJ) {
            const int tj = min(TJ, n - j0);
            __syncthreads();
            for (int t = tid; t < tj*(CQ/4); t += 128) {
                int r = t >> 2, c4 = t & 3;
                ((float4*)s_k)[t] = ((const float4*)(kb + (size_t)sorted[j0 + r]*CQ))[c4];
            }
            for (int t = tid; t < tj*(CC/4); t += 128) {
                int r = t >> 4, c4 = t & 15;
                ((float4*)s_v)[(r*(CC/4)) + c4] = ((const float4*)(vb + (size_t)sorted[j0 + r]*CC))[c4];
            }
            __syncthreads();
            if (act) {
                for (int j = 0; j < tj; j++) {
                    const ulonglong2* kk = (const ulonglong2*)(s_k + j*CQ);
                    unsigned long long s2 = 0ull;
#pragma unroll
                    for (int c = 0; c < CQ/4; c++) {
                        ulonglong2 kp = kk[c];
                        s2 = ffma2(q2[2*c],   kp.x, s2);
                        s2 = ffma2(q2[2*c+1], kp.y, s2);
                    }
                    float slo, shi; unpack2(s2, slo, shi);
                    float w = __expf(slo + shi - SHIFT);
                    Z += w;
                    unsigned long long w2 = pack2(w, w);
                    const ulonglong2* vv = (const ulonglong2*)(s_v + j*CC);
#pragma unroll
                    for (int c = 0; c < CC/4; c++) {
                        ulonglong2 vp = vv[c];
                        acc2[2*c]   = ffma2(w2, vp.x, acc2[2*c]);
                        acc2[2*c+1] = ffma2(w2, vp.y, acc2[2*c+1]);
                    }
                }
            }
        }

        if (act) {
            float inv = 1.0f / Z;
            unsigned int hw[CC/2];
#pragma unroll
            for (int c = 0; c < CC/2; c++) {
                float a0, a1; unpack2(acc2[c], a0, a1);
                __half2 h2 = __floats2half2_rn(a0*inv, a1*inv);
                hw[c] = *(unsigned int*)&h2;
            }
            uint4* ap = (uint4*)(ab + (size_t)gi*CC);
#pragma unroll
            for (int g = 0; g < CC/8; g++)
                ap[g] = make_uint4(hw[4*g], hw[4*g+1], hw[4*g+2], hw[4*g+3]);
        }
    }
}

// ---------------- K3: projection + residual + fused stats (64-token tiles) ----------------
__global__ void __launch_bounds__(256) k_proj(const float* __restrict__ x,
    const float* __restrict__ Wo, const float* __restrict__ bo,
    const float* __restrict__ gamma)
{
    __shared__ __align__(16) float sA[PTOK*65];
    __shared__ __align__(16) float sW[CC*CC];
    const int t = threadIdx.x;
    const int b = blockIdx.y;
    const int l0 = blockIdx.x * PTOK;

    for (int i = t; i < CC*CC; i += 256) sW[i] = Wo[i];
    {
        const size_t base2 = (((size_t)b*LL + l0)*CC) >> 1;
        const size_t plane = ((size_t)BB*LL*CC) >> 1;
        const __half2* A = (const __half2*)g_acch;
        for (int i = t; i < PTOK*(CC/2); i += 256) {
            float2 f0 = __half22float2(A[0*plane + base2 + i]);
            float2 f1 = __half22float2(A[1*plane + base2 + i]);
            float2 f2 = __half22float2(A[2*plane + base2 + i]);
            float2 f3 = __half22float2(A[3*plane + base2 + i]);
            int tok = i >> 5, c2 = i & 31;
            sA[tok*65 + 2*c2]     = (f0.x + f1.x + f2.x + f3.x) * 0.25f;
            sA[tok*65 + 2*c2 + 1] = (f0.y + f1.y + f2.y + f3.y) * 0.25f;
        }
    }
    __syncthreads();

    const int w  = t >> 5;   // warp -> channels w*8..w*8+7
    const int ln = t & 31;   // token lane
    const float g = gamma[0];

    float accA[8], accB[8];
#pragma unroll
    for (int k = 0; k < 8; k++) { accA[k] = bo[w*8 + k]; accB[k] = accA[k]; }

#pragma unroll 4
    for (int cin = 0; cin < CC; cin++) {
        float a1 = sA[ln*65 + cin];
        float a2 = sA[(ln+32)*65 + cin];
#pragma unroll
        for (int k = 0; k < 8; k++) {
            float wv = sW[(w*8 + k)*CC + cin];
            accA[k] += wv * a1;
            accB[k] += wv * a2;
        }
    }

    const int blk = b*(LL/PTOK) + blockIdx.x;
#pragma unroll
    for (int k = 0; k < 8; k++) {
        int c = w*8 + k;
        size_t i1 = ((size_t)b*CC + c)*LL + l0 + ln;
        size_t i2 = i1 + 32;
        float o1 = g*accA[k] + x[i1];
        float o2 = g*accB[k] + x[i2];
        g_pre[i1] = o1;
        g_pre[i2] = o2;
        float s  = o1 + o2;
        float sq = o1*o1 + o2*o2;
#pragma unroll
        for (int off = 16; off > 0; off >>= 1) {
            s  += __shfl_down_sync(0xffffffffu, s,  off);
            sq += __shfl_down_sync(0xffffffffu, sq, off);
        }
        if (ln == 0) {
            g_psum[c*NPB + blk] = s;
            g_psq [c*NPB + blk] = sq;
        }
    }
}

// ---------------- K4: per-(b,c) block — reduce channel partials + apply BN ----------------
__global__ void __launch_bounds__(256) k_norm(float* __restrict__ out,
    const float* __restrict__ bn_w, const float* __restrict__ bn_b)
{
    const int c = blockIdx.x;   // channel
    const int b = blockIdx.y;   // batch
    const int t = threadIdx.x;

    // deterministic reduce of this channel's 256 partials (same tree in every block)
    __shared__ double rs[256], rs2[256];
    __shared__ float s_scale, s_shift;
    rs[t]  = (double)g_psum[c*NPB + t];
    rs2[t] = (double)g_psq [c*NPB + t];
    __syncthreads();
    for (int o = 128; o > 0; o >>= 1) {
        if (t < o) { rs[t] += rs[t+o]; rs2[t] += rs2[t+o]; }
        __syncthreads();
    }
    if (t == 0) {
        double mean = rs[0] * (1.0/(BB*LL));
        double var  = rs2[0] * (1.0/(BB*LL)) - mean*mean;
        float rstd = rsqrtf((float)var + EPSV);
        float sc = rstd * bn_w[c];
        s_scale = sc;
        s_shift = bn_b[c] - (float)mean * sc;
    }
    __syncthreads();

    const float sc = s_scale, sh = s_shift;
    const size_t row4 = (((size_t)b*CC + c)*LL) >> 2;   // float4 base
    const float4* p4 = (const float4*)g_pre + row4;
    float4* o4 = (float4*)out + row4;
#pragma unroll
    for (int i = t; i < LL/4; i += 256) {
        float4 p = p4[i];
        o4[i] = make_float4(p.x*sc + sh, p.y*sc + sh, p.z*sc + sh, p.w*sc + sh);
    }
}

// ---------------- launch ----------------
extern "C" void kernel_launch(void* const* d_in, const int* in_sizes, int n_in,
                              void* d_out, int out_size)
{
    const float* x     = (const float*)d_in[0];
    const int*   hash  = (const int*)  d_in[1];
    const float* Wq    = (const float*)d_in[2];
    const float* bq    = (const float*)d_in[3];
    const float* Wk    = (const float*)d_in[4];
    const float* bk    = (const float*)d_in[5];
    const float* Wv    = (const float*)d_in[6];
    const float* bv    = (const float*)d_in[7];
    const float* Wo    = (const float*)d_in[8];
    const float* bo    = (const float*)d_in[9];
    const float* gamma = (const float*)d_in[10];
    const float* bnw   = (const float*)d_in[11];
    const float* bnb   = (const float*)d_in[12];
    float* out = (float*)d_out;

    k_pre  <<<dim3(LL/256, BB, 7), 256>>>(x, hash, Wq, bq, Wk, bk, Wv, bv);
    k_attn <<<dim3(NB, NH, BB), 128>>>();
    k_proj <<<dim3(LL/PTOK, BB), 256>>>(x, Wo, bo, gamma);
    k_norm <<<dim3(CC, BB), 256>>>(out, bnw, bnb);
}

// round 7
// speedup vs baseline: 1.3157x; 1.2167x over previous
#include <cuda_runtime.h>
#include <cuda_fp16.h>
#include <cuda_bf16.h>

#define BB 4
#define CC 64
#define LL 4096
#define CQ 16
#define NH 4
#define NB 32
#define TJ 128
#define EPSV 1e-5f
#define SHIFT 20.0f
#define PTOK 64
#define NPB (BB*(LL/PTOK))

// ---------------- scratch ----------------
__device__ float g_q[BB*LL*CQ];
__device__ float g_k[BB*LL*CQ];
__device__ float g_v[BB*LL*CC];
__device__ int   g_sorted[BB*NH*LL];
__device__ int   g_bstart[BB*NH*(NB+1)];
__device__ __align__(16) __half g_acch[NH*BB*LL*CC];
__device__ float g_pre[BB*CC*LL];
__device__ float g_psum[CC*NPB];
__device__ float g_psq[CC*NPB];

// ---------------- packed f32x2 helpers ----------------
__device__ __forceinline__ unsigned long long ffma2(unsigned long long a,
                                                    unsigned long long b,
                                                    unsigned long long c) {
    unsigned long long d;
    asm("fma.rn.f32x2 %0, %1, %2, %3;" : "=l"(d) : "l"(a), "l"(b), "l"(c));
    return d;
}
__device__ __forceinline__ unsigned long long pack2(float lo, float hi) {
    unsigned long long r;
    asm("mov.b64 %0, {%1, %2};" : "=l"(r)
        : "r"(__float_as_uint(lo)), "r"(__float_as_uint(hi)));
    return r;
}
__device__ __forceinline__ void unpack2(unsigned long long v, float& lo, float& hi) {
    unsigned int a, b;
    asm("mov.b64 {%0, %1}, %2;" : "=r"(a), "=r"(b) : "l"(v));
    lo = __uint_as_float(a); hi = __uint_as_float(b);
}

// ---------------- K1: fused qkv convs (z<6) + bucket sort (z==6) ----------------
__global__ void __launch_bounds__(256) k_pre(const float* __restrict__ x,
    const int* __restrict__ hash,
    const float* __restrict__ Wq, const float* __restrict__ bq,
    const float* __restrict__ Wk, const float* __restrict__ bk,
    const float* __restrict__ Wv, const float* __restrict__ bv)
{
    const int t = threadIdx.x;
    const int z = blockIdx.z;

    if (z == 6) {
        if (blockIdx.x >= NH) return;
        const int h = blockIdx.x, b = blockIdx.y;
        const int* hb = hash + ((size_t)b*NH + h)*LL;

        __shared__ unsigned short cnt[256][NB];
        __shared__ int tot[NB];
        __shared__ int bstart[NB+1];

        for (int k = 0; k < NB; k++) cnt[t][k] = 0;
        __syncthreads();

        const int base = t * 16;
#pragma unroll
        for (int e = 0; e < 16; e++) cnt[t][hb[base + e]]++;
        __syncthreads();

        if (t < NB) {
            int s = 0;
            for (int r = 0; r < 256; r++) {
                unsigned short v = cnt[r][t];
                cnt[r][t] = (unsigned short)s;
                s += v;
            }
            tot[t] = s;
        }
        __syncthreads();
        if (t == 0) {
            int s = 0;
            for (int k = 0; k < NB; k++) { bstart[k] = s; s += tot[k]; }
            bstart[NB] = s;
        }
        __syncthreads();
        if (t < NB + 1) g_bstart[((size_t)b*NH + h)*(NB+1) + t] = bstart[t];

        int* out = g_sorted + ((size_t)b*NH + h)*LL;
#pragma unroll
        for (int e = 0; e < 16; e++) {
            int l = base + e;
            int bk = hb[l];
            out[bstart[bk] + cnt[t][bk]] = l;
            cnt[t][bk]++;
        }
        return;
    }

    __shared__ __align__(16) float sW[16*CC];
    __shared__ float sb[16];
    const int b = blockIdx.y;
    const int l = blockIdx.x * 256 + t;

    const float* W; const float* bias;
    if (z == 0)      { W = Wq; bias = bq; }
    else if (z == 1) { W = Wk; bias = bk; }
    else             { W = Wv + (z-2)*16*CC; bias = bv + (z-2)*16; }
    for (int i = t; i < 16*CC/4; i += 256) ((float4*)sW)[i] = ((const float4*)W)[i];
    if (t < 16) sb[t] = bias[t];
    __syncthreads();

    const float* xb = x + (size_t)b*CC*LL + l;
    float xr[CC];
#pragma unroll
    for (int c = 0; c < CC; c++) xr[c] = xb[(size_t)c*LL];

    float out[16];
#pragma unroll 4
    for (int o = 0; o < 16; o++) {
        float a = sb[o];
        const float4* w = (const float4*)&sW[o*CC];
#pragma unroll
        for (int c4 = 0; c4 < CC/4; c4++) {
            float4 w4 = w[c4];
            a += w4.x*xr[4*c4] + w4.y*xr[4*c4+1] + w4.z*xr[4*c4+2] + w4.w*xr[4*c4+3];
        }
        out[o] = a;
    }

    float4* dst;
    if (z == 0)      dst = (float4*)(g_q + ((size_t)b*LL + l)*CQ);
    else if (z == 1) dst = (float4*)(g_k + ((size_t)b*LL + l)*CQ);
    else             dst = (float4*)(g_v + ((size_t)b*LL + l)*CC + (z-2)*16);
#pragma unroll
    for (int i = 0; i < 4; i++)
        dst[i] = make_float4(out[4*i], out[4*i+1], out[4*i+2], out[4*i+3]);
}

// ---------------- K2: bucket softmax attention, dual-query per thread ----------------
__global__ void __launch_bounds__(128) k_attn()
{
    const int bucket = blockIdx.x, h = blockIdx.y, b = blockIdx.z;
    const int bh = b*NH + h;
    const int start = g_bstart[bh*(NB+1) + bucket];
    const int end   = g_bstart[bh*(NB+1) + bucket + 1];
    const int n = end - start;
    if (n <= 0) return;

    const int* __restrict__ sorted = g_sorted + (size_t)bh*LL + start;
    const float* __restrict__ kb = g_k + (size_t)b*LL*CQ;
    const float* __restrict__ vb = g_v + (size_t)b*LL*CC;
    const float* __restrict__ qb = g_q + (size_t)b*LL*CQ;
    __half* __restrict__ ab = g_acch + (((size_t)h*BB + b)*LL)*CC;

    __shared__ __align__(16) float s_k[TJ*CQ];
    __shared__ __align__(16) float s_v[TJ*CC];

    const int tid = threadIdx.x;

    // outer loop in steps of 256 queries (one key pass per step)
    for (int q0 = 0; q0 < n; q0 += 256) {
        const int qiA = q0 + tid;
        const int qiB = q0 + tid + 128;
        const bool actA = qiA < n;
        const bool actB = qiB < n;
        // warp-uniform: does this warp carry any B query?
        const bool warpHasB = (q0 + (tid & ~31) + 128) < n;

        int giA = 0, giB = 0;
        unsigned long long q2a[CQ/2], q2b[CQ/2];
#pragma unroll
        for (int c = 0; c < CQ/2; c++) { q2a[c] = 0ull; q2b[c] = 0ull; }
        if (actA) {
            giA = sorted[qiA];
            const float4* qs = (const float4*)(qb + (size_t)giA*CQ);
#pragma unroll
            for (int c4 = 0; c4 < CQ/4; c4++) {
                float4 v4 = qs[c4];
                q2a[2*c4]   = pack2(v4.x, v4.y);
                q2a[2*c4+1] = pack2(v4.z, v4.w);
            }
        }
        if (actB) {
            giB = sorted[qiB];
            const float4* qs = (const float4*)(qb + (size_t)giB*CQ);
#pragma unroll
            for (int c4 = 0; c4 < CQ/4; c4++) {
                float4 v4 = qs[c4];
                q2b[2*c4]   = pack2(v4.x, v4.y);
                q2b[2*c4+1] = pack2(v4.z, v4.w);
            }
        }

        unsigned long long accA[CC/2], accB[CC/2];
#pragma unroll
        for (int c = 0; c < CC/2; c++) { accA[c] = 0ull; accB[c] = 0ull; }
        float Za = 0.f, Zb = 0.f;

        for (int j0 = 0; j0 < n; j0 += TJ) {
            const int tj = min(TJ, n - j0);
            __syncthreads();
            for (int t = tid; t < tj*(CQ/4); t += 128) {
                int r = t >> 2, c4 = t & 3;
                ((float4*)s_k)[t] = ((const float4*)(kb + (size_t)sorted[j0 + r]*CQ))[c4];
            }
            for (int t = tid; t < tj*(CC/4); t += 128) {
                int r = t >> 4, c4 = t & 15;
                ((float4*)s_v)[(r*(CC/4)) + c4] = ((const float4*)(vb + (size_t)sorted[j0 + r]*CC))[c4];
            }
            __syncthreads();

            if (warpHasB) {
                // dual-query loop
                for (int j = 0; j < tj; j++) {
                    const ulonglong2* kk = (const ulonglong2*)(s_k + j*CQ);
                    unsigned long long sa = 0ull, sb2 = 0ull;
#pragma unroll
                    for (int c = 0; c < CQ/4; c++) {
                        ulonglong2 kp = kk[c];
                        sa  = ffma2(q2a[2*c],   kp.x, sa);
                        sa  = ffma2(q2a[2*c+1], kp.y, sa);
                        sb2 = ffma2(q2b[2*c],   kp.x, sb2);
                        sb2 = ffma2(q2b[2*c+1], kp.y, sb2);
                    }
                    float alo, ahi, blo, bhi;
                    unpack2(sa, alo, ahi);
                    unpack2(sb2, blo, bhi);
                    float wa = __expf(alo + ahi - SHIFT);
                    float wb = __expf(blo + bhi - SHIFT);
                    Za += wa; Zb += wb;
                    unsigned long long wa2 = pack2(wa, wa);
                    unsigned long long wb2 = pack2(wb, wb);
                    const ulonglong2* vv = (const ulonglong2*)(s_v + j*CC);
#pragma unroll
                    for (int c = 0; c < CC/4; c++) {
                        ulonglong2 vp = vv[c];
                        accA[2*c]   = ffma2(wa2, vp.x, accA[2*c]);
                        accA[2*c+1] = ffma2(wa2, vp.y, accA[2*c+1]);
                        accB[2*c]   = ffma2(wb2, vp.x, accB[2*c]);
                        accB[2*c+1] = ffma2(wb2, vp.y, accB[2*c+1]);
                    }
                }
            } else if (actA) {
                // single-query loop
                for (int j = 0; j < tj; j++) {
                    const ulonglong2* kk = (const ulonglong2*)(s_k + j*CQ);
                    unsigned long long sa = 0ull;
#pragma unroll
                    for (int c = 0; c < CQ/4; c++) {
                        ulonglong2 kp = kk[c];
                        sa = ffma2(q2a[2*c],   kp.x, sa);
                        sa = ffma2(q2a[2*c+1], kp.y, sa);
                    }
                    float alo, ahi; unpack2(sa, alo, ahi);
                    float wa = __expf(alo + ahi - SHIFT);
                    Za += wa;
                    unsigned long long wa2 = pack2(wa, wa);
                    const ulonglong2* vv = (const ulonglong2*)(s_v + j*CC);
#pragma unroll
                    for (int c = 0; c < CC/4; c++) {
                        ulonglong2 vp = vv[c];
                        accA[2*c]   = ffma2(wa2, vp.x, accA[2*c]);
                        accA[2*c+1] = ffma2(wa2, vp.y, accA[2*c+1]);
                    }
                }
            }
        }

        if (actA) {
            float inv = 1.0f / Za;
            unsigned int hw[CC/2];
#pragma unroll
            for (int c = 0; c < CC/2; c++) {
                float a0, a1; unpack2(accA[c], a0, a1);
                __half2 h2 = __floats2half2_rn(a0*inv, a1*inv);
                hw[c] = *(unsigned int*)&h2;
            }
            uint4* ap = (uint4*)(ab + (size_t)giA*CC);
#pragma unroll
            for (int g = 0; g < CC/8; g++)
                ap[g] = make_uint4(hw[4*g], hw[4*g+1], hw[4*g+2], hw[4*g+3]);
        }
        if (actB) {
            float inv = 1.0f / Zb;
            unsigned int hw[CC/2];
#pragma unroll
            for (int c = 0; c < CC/2; c++) {
                float a0, a1; unpack2(accB[c], a0, a1);
                __half2 h2 = __floats2half2_rn(a0*inv, a1*inv);
                hw[c] = *(unsigned int*)&h2;
            }
            uint4* ap = (uint4*)(ab + (size_t)giB*CC);
#pragma unroll
            for (int g = 0; g < CC/8; g++)
                ap[g] = make_uint4(hw[4*g], hw[4*g+1], hw[4*g+2], hw[4*g+3]);
        }
    }
}

// ---------------- K3: projection + residual + fused stats ----------------
__global__ void __launch_bounds__(256) k_proj(const float* __restrict__ x,
    const float* __restrict__ Wo, const float* __restrict__ bo,
    const float* __restrict__ gamma)
{
    __shared__ __align__(16) float sA[PTOK*65];
    __shared__ __align__(16) float sW[CC*CC];
    const int t = threadIdx.x;
    const int b = blockIdx.y;
    const int l0 = blockIdx.x * PTOK;

    for (int i = t; i < CC*CC/4; i += 256) ((float4*)sW)[i] = ((const float4*)Wo)[i];
    {
        const size_t base2 = (((size_t)b*LL + l0)*CC) >> 1;
        const size_t plane = ((size_t)BB*LL*CC) >> 1;
        const __half2* A = (const __half2*)g_acch;
        for (int i = t; i < PTOK*(CC/2); i += 256) {
            float2 f0 = __half22float2(A[0*plane + base2 + i]);
            float2 f1 = __half22float2(A[1*plane + base2 + i]);
            float2 f2 = __half22float2(A[2*plane + base2 + i]);
            float2 f3 = __half22float2(A[3*plane + base2 + i]);
            int tok = i >> 5, c2 = i & 31;
            sA[tok*65 + 2*c2]     = (f0.x + f1.x + f2.x + f3.x) * 0.25f;
            sA[tok*65 + 2*c2 + 1] = (f0.y + f1.y + f2.y + f3.y) * 0.25f;
        }
    }
    __syncthreads();

    const int w  = t >> 5;
    const int ln = t & 31;
    const float g = gamma[0];

    float accA[8], accB[8];
#pragma unroll
    for (int k = 0; k < 8; k++) { accA[k] = bo[w*8 + k]; accB[k] = accA[k]; }

#pragma unroll 4
    for (int cin = 0; cin < CC; cin++) {
        float a1 = sA[ln*65 + cin];
        float a2 = sA[(ln+32)*65 + cin];
#pragma unroll
        for (int k = 0; k < 8; k++) {
            float wv = sW[(w*8 + k)*CC + cin];
            accA[k] += wv * a1;
            accB[k] += wv * a2;
        }
    }

    const int blk = b*(LL/PTOK) + blockIdx.x;
#pragma unroll
    for (int k = 0; k < 8; k++) {
        int c = w*8 + k;
        size_t i1 = ((size_t)b*CC + c)*LL + l0 + ln;
        size_t i2 = i1 + 32;
        float o1 = g*accA[k] + x[i1];
        float o2 = g*accB[k] + x[i2];
        g_pre[i1] = o1;
        g_pre[i2] = o2;
        float s  = o1 + o2;
        float sq = o1*o1 + o2*o2;
#pragma unroll
        for (int off = 16; off > 0; off >>= 1) {
            s  += __shfl_down_sync(0xffffffffu, s,  off);
            sq += __shfl_down_sync(0xffffffffu, sq, off);
        }
        if (ln == 0) {
            g_psum[c*NPB + blk] = s;
            g_psq [c*NPB + blk] = sq;
        }
    }
}

// ---------------- K4: reduce channel partials + apply BN (L-split x2) ----------------
__global__ void __launch_bounds__(256) k_norm(float* __restrict__ out,
    const float* __restrict__ bn_w, const float* __restrict__ bn_b)
{
    const int c = blockIdx.x;
    const int b = blockIdx.y;
    const int half = blockIdx.z;
    const int t = threadIdx.x;

    __shared__ double rs[256], rs2[256];
    __shared__ float s_scale, s_shift;
    rs[t]  = (double)g_psum[c*NPB + t];
    rs2[t] = (double)g_psq [c*NPB + t];
    __syncthreads();
    for (int o = 128; o > 0; o >>= 1) {
        if (t < o) { rs[t] += rs[t+o]; rs2[t] += rs2[t+o]; }
        __syncthreads();
    }
    if (t == 0) {
        double mean = rs[0] * (1.0/(BB*LL));
        double var  = rs2[0] * (1.0/(BB*LL)) - mean*mean;
        float rstd = rsqrtf((float)var + EPSV);
        float sc = rstd * bn_w[c];
        s_scale = sc;
        s_shift = bn_b[c] - (float)mean * sc;
    }
    __syncthreads();

    const float sc = s_scale, sh = s_shift;
    const size_t row4 = ((((size_t)b*CC + c)*LL) >> 2) + half*(LL/8);
    const float4* p4 = (const float4*)g_pre + row4;
    float4* o4 = (float4*)out + row4;
#pragma unroll
    for (int i = t; i < LL/8; i += 256) {
        float4 p = p4[i];
        o4[i] = make_float4(p.x*sc + sh, p.y*sc + sh, p.z*sc + sh, p.w*sc + sh);
    }
}

// ---------------- launch ----------------
extern "C" void kernel_launch(void* const* d_in, const int* in_sizes, int n_in,
                              void* d_out, int out_size)
{
    const float* x     = (const float*)d_in[0];
    const int*   hash  = (const int*)  d_in[1];
    const float* Wq    = (const float*)d_in[2];
    const float* bq    = (const float*)d_in[3];
    const float* Wk    = (const float*)d_in[4];
    const float* bk    = (const float*)d_in[5];
    const float* Wv    = (const float*)d_in[6];
    const float* bv    = (const float*)d_in[7];
    const float* Wo    = (const float*)d_in[8];
    const float* bo    = (const float*)d_in[9];
    const float* gamma = (const float*)d_in[10];
    const float* bnw   = (const float*)d_in[11];
    const float* bnb   = (const float*)d_in[12];
    float* out = (float*)d_out;

    k_pre  <<<dim3(LL/256, BB, 7), 256>>>(x, hash, Wq, bq, Wk, bk, Wv, bv);
    k_attn <<<dim3(NB, NH, BB), 128>>>();
    k_proj <<<dim3(LL/PTOK, BB), 256>>>(x, Wo, bo, gamma);
    k_norm <<<dim3(CC, BB, 2), 256>>>(out, bnw, bnb);
}

// round 11
// speedup vs baseline: 1.3275x; 1.0090x over previous
#include <cuda_runtime.h>
#include <cuda_fp16.h>
#include <cuda_bf16.h>

#define BB 4
#define CC 64
#define LL 4096
#define CQ 16
#define NH 4
#define NB 32
#define TJ 128
#define EPSV 1e-5f
#define SHIFT 20.0f
#define PTOK 64
#define NPB (BB*(LL/PTOK))

// ---------------- scratch ----------------
__device__ float g_q[BB*LL*CQ];
__device__ float g_k[BB*LL*CQ];
__device__ float g_v[BB*LL*CC];
__device__ int   g_sorted[BB*NH*LL];
__device__ int   g_bstart[BB*NH*(NB+1)];
__device__ __align__(16) __half g_acch[NH*BB*LL*CC];
__device__ float g_pre[BB*CC*LL];
__device__ float g_psum[CC*NPB];
__device__ float g_psq[CC*NPB];

// ---------------- packed f32x2 helpers ----------------
__device__ __forceinline__ unsigned long long ffma2(unsigned long long a,
                                                    unsigned long long b,
                                                    unsigned long long c) {
    unsigned long long d;
    asm("fma.rn.f32x2 %0, %1, %2, %3;" : "=l"(d) : "l"(a), "l"(b), "l"(c));
    return d;
}
__device__ __forceinline__ unsigned long long pack2(float lo, float hi) {
    unsigned long long r;
    asm("mov.b64 %0, {%1, %2};" : "=l"(r)
        : "r"(__float_as_uint(lo)), "r"(__float_as_uint(hi)));
    return r;
}
__device__ __forceinline__ void unpack2(unsigned long long v, float& lo, float& hi) {
    unsigned int a, b;
    asm("mov.b64 {%0, %1}, %2;" : "=r"(a), "=r"(b) : "l"(v));
    lo = __uint_as_float(a); hi = __uint_as_float(b);
}

// ---------------- K1: fused qkv convs (z<6) + bucket sort (z==6) ----------------
__global__ void __launch_bounds__(256) k_pre(const float* __restrict__ x,
    const int* __restrict__ hash,
    const float* __restrict__ Wq, const float* __restrict__ bq,
    const float* __restrict__ Wk, const float* __restrict__ bk,
    const float* __restrict__ Wv, const float* __restrict__ bv)
{
    const int t = threadIdx.x;
    const int z = blockIdx.z;

    if (z == 6) {
        if (blockIdx.x >= NH) return;
        const int h = blockIdx.x, b = blockIdx.y;
        const int* hb = hash + ((size_t)b*NH + h)*LL;

        __shared__ unsigned short cnt[256][NB];
        __shared__ int tot[NB];
        __shared__ int bstart[NB+1];

        for (int k = 0; k < NB; k++) cnt[t][k] = 0;
        __syncthreads();

        const int base = t * 16;
#pragma unroll
        for (int e = 0; e < 16; e++) cnt[t][hb[base + e]]++;
        __syncthreads();

        if (t < NB) {
            int s = 0;
            for (int r = 0; r < 256; r++) {
                unsigned short v = cnt[r][t];
                cnt[r][t] = (unsigned short)s;
                s += v;
            }
            tot[t] = s;
        }
        __syncthreads();
        if (t == 0) {
            int s = 0;
            for (int k = 0; k < NB; k++) { bstart[k] = s; s += tot[k]; }
            bstart[NB] = s;
        }
        __syncthreads();
        if (t < NB + 1) g_bstart[((size_t)b*NH + h)*(NB+1) + t] = bstart[t];

        int* out = g_sorted + ((size_t)b*NH + h)*LL;
#pragma unroll
        for (int e = 0; e < 16; e++) {
            int l = base + e;
            int bk = hb[l];
            out[bstart[bk] + cnt[t][bk]] = l;
            cnt[t][bk]++;
        }
        return;
    }

    __shared__ __align__(16) float sW[16*CC];
    __shared__ float sb[16];
    const int b = blockIdx.y;
    const int l = blockIdx.x * 256 + t;

    const float* W; const float* bias;
    if (z == 0)      { W = Wq; bias = bq; }
    else if (z == 1) { W = Wk; bias = bk; }
    else             { W = Wv + (z-2)*16*CC; bias = bv + (z-2)*16; }
    for (int i = t; i < 16*CC/4; i += 256) ((float4*)sW)[i] = ((const float4*)W)[i];
    if (t < 16) sb[t] = bias[t];
    __syncthreads();

    const float* xb = x + (size_t)b*CC*LL + l;
    float xr[CC];
#pragma unroll
    for (int c = 0; c < CC; c++) xr[c] = xb[(size_t)c*LL];

    float out[16];
#pragma unroll 4
    for (int o = 0; o < 16; o++) {
        float a = sb[o];
        const float4* w = (const float4*)&sW[o*CC];
#pragma unroll
        for (int c4 = 0; c4 < CC/4; c4++) {
            float4 w4 = w[c4];
            a += w4.x*xr[4*c4] + w4.y*xr[4*c4+1] + w4.z*xr[4*c4+2] + w4.w*xr[4*c4+3];
        }
        out[o] = a;
    }

    float4* dst;
    if (z == 0)      dst = (float4*)(g_q + ((size_t)b*LL + l)*CQ);
    else if (z == 1) dst = (float4*)(g_k + ((size_t)b*LL + l)*CQ);
    else             dst = (float4*)(g_v + ((size_t)b*LL + l)*CC + (z-2)*16);
#pragma unroll
    for (int i = 0; i < 4; i++)
        dst[i] = make_float4(out[4*i], out[4*i+1], out[4*i+2], out[4*i+3]);
}

// ---------------- K2: bucket softmax attention, dual-query per thread ----------------
__global__ void __launch_bounds__(128) k_attn()
{
    const int bucket = blockIdx.x, h = blockIdx.y, b = blockIdx.z;
    const int bh = b*NH + h;
    const int start = g_bstart[bh*(NB+1) + bucket];
    const int end   = g_bstart[bh*(NB+1) + bucket + 1];
    const int n = end - start;
    if (n <= 0) return;

    const int* __restrict__ sorted = g_sorted + (size_t)bh*LL + start;
    const float* __restrict__ kb = g_k + (size_t)b*LL*CQ;
    const float* __restrict__ vb = g_v + (size_t)b*LL*CC;
    const float* __restrict__ qb = g_q + (size_t)b*LL*CQ;
    __half* __restrict__ ab = g_acch + (((size_t)h*BB + b)*LL)*CC;

    __shared__ __align__(16) float s_k[TJ*CQ];
    __shared__ __align__(16) float s_v[TJ*CC];

    const int tid = threadIdx.x;

    for (int q0 = 0; q0 < n; q0 += 256) {
        const int qiA = q0 + tid;
        const int qiB = q0 + tid + 128;
        const bool actA = qiA < n;
        const bool actB = qiB < n;
        const bool warpHasB = (q0 + (tid & ~31) + 128) < n;

        int giA = 0, giB = 0;
        unsigned long long q2a[CQ/2], q2b[CQ/2];
#pragma unroll
        for (int c = 0; c < CQ/2; c++) { q2a[c] = 0ull; q2b[c] = 0ull; }
        if (actA) {
            giA = sorted[qiA];
            const float4* qs = (const float4*)(qb + (size_t)giA*CQ);
#pragma unroll
            for (int c4 = 0; c4 < CQ/4; c4++) {
                float4 v4 = qs[c4];
                q2a[2*c4]   = pack2(v4.x, v4.y);
                q2a[2*c4+1] = pack2(v4.z, v4.w);
            }
        }
        if (actB) {
            giB = sorted[qiB];
            const float4* qs = (const float4*)(qb + (size_t)giB*CQ);
#pragma unroll
            for (int c4 = 0; c4 < CQ/4; c4++) {
                float4 v4 = qs[c4];
                q2b[2*c4]   = pack2(v4.x, v4.y);
                q2b[2*c4+1] = pack2(v4.z, v4.w);
            }
        }

        unsigned long long accA[CC/2], accB[CC/2];
#pragma unroll
        for (int c = 0; c < CC/2; c++) { accA[c] = 0ull; accB[c] = 0ull; }
        float Za = 0.f, Zb = 0.f;

        for (int j0 = 0; j0 < n; j0 += TJ) {
            const int tj = min(TJ, n - j0);
            __syncthreads();
            for (int t = tid; t < tj*(CQ/4); t += 128) {
                int r = t >> 2, c4 = t & 3;
                ((float4*)s_k)[t] = ((const float4*)(kb + (size_t)sorted[j0 + r]*CQ))[c4];
            }
            for (int t = tid; t < tj*(CC/4); t += 128) {
                int r = t >> 4, c4 = t & 15;
                ((float4*)s_v)[(r*(CC/4)) + c4] = ((const float4*)(vb + (size_t)sorted[j0 + r]*CC))[c4];
            }
            __syncthreads();

            if (warpHasB) {
                for (int j = 0; j < tj; j++) {
                    const ulonglong2* kk = (const ulonglong2*)(s_k + j*CQ);
                    unsigned long long sa = 0ull, sb2 = 0ull;
#pragma unroll
                    for (int c = 0; c < CQ/4; c++) {
                        ulonglong2 kp = kk[c];
                        sa  = ffma2(q2a[2*c],   kp.x, sa);
                        sa  = ffma2(q2a[2*c+1], kp.y, sa);
                        sb2 = ffma2(q2b[2*c],   kp.x, sb2);
                        sb2 = ffma2(q2b[2*c+1], kp.y, sb2);
                    }
                    float alo, ahi, blo, bhi;
                    unpack2(sa, alo, ahi);
                    unpack2(sb2, blo, bhi);
                    float wa = __expf(alo + ahi - SHIFT);
                    float wb = __expf(blo + bhi - SHIFT);
                    Za += wa; Zb += wb;
                    unsigned long long wa2 = pack2(wa, wa);
                    unsigned long long wb2 = pack2(wb, wb);
                    const ulonglong2* vv = (const ulonglong2*)(s_v + j*CC);
#pragma unroll
                    for (int c = 0; c < CC/4; c++) {
                        ulonglong2 vp = vv[c];
                        accA[2*c]   = ffma2(wa2, vp.x, accA[2*c]);
                        accA[2*c+1] = ffma2(wa2, vp.y, accA[2*c+1]);
                        accB[2*c]   = ffma2(wb2, vp.x, accB[2*c]);
                        accB[2*c+1] = ffma2(wb2, vp.y, accB[2*c+1]);
                    }
                }
            } else if (actA) {
                for (int j = 0; j < tj; j++) {
                    const ulonglong2* kk = (const ulonglong2*)(s_k + j*CQ);
                    unsigned long long sa = 0ull;
#pragma unroll
                    for (int c = 0; c < CQ/4; c++) {
                        ulonglong2 kp = kk[c];
                        sa = ffma2(q2a[2*c],   kp.x, sa);
                        sa = ffma2(q2a[2*c+1], kp.y, sa);
                    }
                    float alo, ahi; unpack2(sa, alo, ahi);
                    float wa = __expf(alo + ahi - SHIFT);
                    Za += wa;
                    unsigned long long wa2 = pack2(wa, wa);
                    const ulonglong2* vv = (const ulonglong2*)(s_v + j*CC);
#pragma unroll
                    for (int c = 0; c < CC/4; c++) {
                        ulonglong2 vp = vv[c];
                        accA[2*c]   = ffma2(wa2, vp.x, accA[2*c]);
                        accA[2*c+1] = ffma2(wa2, vp.y, accA[2*c+1]);
                    }
                }
            }
        }

        if (actA) {
            float inv = 1.0f / Za;
            unsigned int hw[CC/2];
#pragma unroll
            for (int c = 0; c < CC/2; c++) {
                float a0, a1; unpack2(accA[c], a0, a1);
                __half2 h2 = __floats2half2_rn(a0*inv, a1*inv);
                hw[c] = *(unsigned int*)&h2;
            }
            uint4* ap = (uint4*)(ab + (size_t)giA*CC);
#pragma unroll
            for (int g = 0; g < CC/8; g++)
                ap[g] = make_uint4(hw[4*g], hw[4*g+1], hw[4*g+2], hw[4*g+3]);
        }
        if (actB) {
            float inv = 1.0f / Zb;
            unsigned int hw[CC/2];
#pragma unroll
            for (int c = 0; c < CC/2; c++) {
                float a0, a1; unpack2(accB[c], a0, a1);
                __half2 h2 = __floats2half2_rn(a0*inv, a1*inv);
                hw[c] = *(unsigned int*)&h2;
            }
            uint4* ap = (uint4*)(ab + (size_t)giB*CC);
#pragma unroll
            for (int g = 0; g < CC/8; g++)
                ap[g] = make_uint4(hw[4*g], hw[4*g+1], hw[4*g+2], hw[4*g+3]);
        }
    }
}

// ---------------- K3: projection + residual + stats, channel-split x2 ----------------
__global__ void __launch_bounds__(256) k_proj(const float* __restrict__ x,
    const float* __restrict__ Wo, const float* __restrict__ bo,
    const float* __restrict__ gamma)
{
    __shared__ __align__(16) float sA[PTOK*65];      // 64 tokens x 64 cin
    __shared__ __align__(16) float sW[32*CC];        // 32 out-ch x 64 cin (8KB)
    const int t = threadIdx.x;
    const int b = blockIdx.y;
    const int zc = blockIdx.z;                        // channel half: 0 or 1
    const int l0 = blockIdx.x * PTOK;

    for (int i = t; i < 32*CC/4; i += 256)
        ((float4*)sW)[i] = ((const float4*)(Wo + zc*32*CC))[i];
    {
        const size_t base2 = (((size_t)b*LL + l0)*CC) >> 1;
        const size_t plane = ((size_t)BB*LL*CC) >> 1;
        const __half2* A = (const __half2*)g_acch;
        for (int i = t; i < PTOK*(CC/2); i += 256) {
            float2 f0 = __half22float2(A[0*plane + base2 + i]);
            float2 f1 = __half22float2(A[1*plane + base2 + i]);
            float2 f2 = __half22float2(A[2*plane + base2 + i]);
            float2 f3 = __half22float2(A[3*plane + base2 + i]);
            int tok = i >> 5, c2 = i & 31;
            sA[tok*65 + 2*c2]     = (f0.x + f1.x + f2.x + f3.x) * 0.25f;
            sA[tok*65 + 2*c2 + 1] = (f0.y + f1.y + f2.y + f3.y) * 0.25f;
        }
    }
    __syncthreads();

    const int w  = t >> 5;   // warp 0..7 -> 4 channels each
    const int ln = t & 31;   // token lane
    const float g = gamma[0];

    float accA[4], accB[4];
#pragma unroll
    for (int k = 0; k < 4; k++) { accA[k] = bo[zc*32 + w*4 + k]; accB[k] = accA[k]; }

#pragma unroll 4
    for (int cin = 0; cin < CC; cin++) {
        float a1 = sA[ln*65 + cin];
        float a2 = sA[(ln+32)*65 + cin];
#pragma unroll
        for (int k = 0; k < 4; k++) {
            float wv = sW[(w*4 + k)*CC + cin];
            accA[k] += wv * a1;
            accB[k] += wv * a2;
        }
    }

    const int blk = b*(LL/PTOK) + blockIdx.x;
#pragma unroll
    for (int k = 0; k < 4; k++) {
        int c = zc*32 + w*4 + k;
        size_t i1 = ((size_t)b*CC + c)*LL + l0 + ln;
        size_t i2 = i1 + 32;
        float o1 = g*accA[k] + x[i1];
        float o2 = g*accB[k] + x[i2];
        g_pre[i1] = o1;
        g_pre[i2] = o2;
        float s  = o1 + o2;
        float sq = o1*o1 + o2*o2;
#pragma unroll
        for (int off = 16; off > 0; off >>= 1) {
            s  += __shfl_down_sync(0xffffffffu, s,  off);
            sq += __shfl_down_sync(0xffffffffu, sq, off);
        }
        if (ln == 0) {
            g_psum[c*NPB + blk] = s;
            g_psq [c*NPB + blk] = sq;
        }
    }
}

// ---------------- K4: warp-shuffle reduce + BN apply (L-split x2) ----------------
__global__ void __launch_bounds__(256) k_norm(float* __restrict__ out,
    const float* __restrict__ bn_w, const float* __restrict__ bn_b)
{
    const int c = blockIdx.x;
    const int b = blockIdx.y;
    const int half = blockIdx.z;
    const int t = threadIdx.x;
    const int w = t >> 5, ln = t & 31;

    __shared__ double ws[8], ws2[8];
    __shared__ float s_scale, s_shift;

    // each thread one partial; intra-warp shuffle reduce (deterministic fixed tree)
    double s  = (double)g_psum[c*NPB + t];
    double s2 = (double)g_psq [c*NPB + t];
#pragma unroll
    for (int off = 16; off > 0; off >>= 1) {
        s  += __shfl_down_sync(0xffffffffu, s,  off);
        s2 += __shfl_down_sync(0xffffffffu, s2, off);
    }
    if (ln == 0) { ws[w] = s; ws2[w] = s2; }
    __syncthreads();
    if (t == 0) {
        double ts = 0.0, ts2 = 0.0;
#pragma unroll
        for (int i = 0; i < 8; i++) { ts += ws[i]; ts2 += ws2[i]; }
        double mean = ts * (1.0/(BB*LL));
        double var  = ts2 * (1.0/(BB*LL)) - mean*mean;
        float rstd = rsqrtf((float)var + EPSV);
        float sc = rstd * bn_w[c];
        s_scale = sc;
        s_shift = bn_b[c] - (float)mean * sc;
    }
    __syncthreads();

    const float sc = s_scale, sh = s_shift;
    const size_t row4 = ((((size_t)b*CC + c)*LL) >> 2) + half*(LL/8);
    const float4* p4 = (const float4*)g_pre + row4;
    float4* o4 = (float4*)out + row4;
#pragma unroll
    for (int i = t; i < LL/8; i += 256) {
        float4 p = p4[i];
        o4[i] = make_float4(p.x*sc + sh, p.y*sc + sh, p.z*sc + sh, p.w*sc + sh);
    }
}

// ---------------- launch ----------------
extern "C" void kernel_launch(void* const* d_in, const int* in_sizes, int n_in,
                              void* d_out, int out_size)
{
    const float* x     = (const float*)d_in[0];
    const int*   hash  = (const int*)  d_in[1];
    const float* Wq    = (const float*)d_in[2];
    const float* bq    = (const float*)d_in[3];
    const float* Wk    = (const float*)d_in[4];
    const float* bk    = (const float*)d_in[5];
    const float* Wv    = (const float*)d_in[6];
    const float* bv    = (const float*)d_in[7];
    const float* Wo    = (const float*)d_in[8];
    const float* bo    = (const float*)d_in[9];
    const float* gamma = (const float*)d_in[10];
    const float* bnw   = (const float*)d_in[11];
    const float* bnb   = (const float*)d_in[12];
    float* out = (float*)d_out;

    k_pre  <<<dim3(LL/256, BB, 7), 256>>>(x, hash, Wq, bq, Wk, bk, Wv, bv);
    k_attn <<<dim3(NB, NH, BB), 128>>>();
    k_proj <<<dim3(LL/PTOK, BB, 2), 256>>>(x, Wo, bo, gamma);
    k_norm <<<dim3(CC, BB, 2), 256>>>(out, bnw, bnb);
}